// round 15
// baseline (speedup 1.0000x reference)
#include <cuda_runtime.h>
#include <cuda_fp16.h>
#include <math_constants.h>
#include <cstdint>

// Problem constants
#define BB 4
#define SS 2048
#define DD 1024
#define HH 16
#define DK 64
#define MM (BB*SS)          // 8192 rows
#define KDIM 1024

// Scratch in device globals (no allocation allowed)
__device__ __half g_xh[MM*DD];           // f16 x (row-major)
__device__ __half g_Wh[4][DD*DD];        // f16 TRANSPOSED weights [n][k] (q,k,v,o)
__device__ __half g_Qh[BB*HH*SS*DK];     // [b,h,s,d]
__device__ __half g_Kh[BB*HH*SS*DK];     // [b,h,s,d]
__device__ __half g_Vh[BB*HH*SS*DK];     // [b,h,s,d]  (PV uses ldmatrix.trans)
__device__ __half g_ctxh[BB*SS*DD];      // f16 ctx

#define ONES_H2 0x3C003C00u
#define LOG2E 1.4426950408889634f

__device__ __forceinline__ uint32_t packh2(float lo, float hi) {
    __half2 h = __float22half2_rn(make_float2(lo, hi));
    return *(uint32_t*)&h;
}
__device__ __forceinline__ uint32_t ex2h2(uint32_t a) {
    uint32_t d;
    asm("ex2.approx.f16x2 %0, %1;" : "=r"(d) : "r"(a));
    return d;
}

__device__ __forceinline__ void mma_f16(float& d0, float& d1, float& d2, float& d3,
                                        uint32_t a0, uint32_t a1, uint32_t a2, uint32_t a3,
                                        uint32_t b0, uint32_t b1) {
    asm volatile(
        "mma.sync.aligned.m16n8k16.row.col.f32.f16.f16.f32 "
        "{%0,%1,%2,%3}, {%4,%5,%6,%7}, {%8,%9}, {%0,%1,%2,%3};"
        : "+f"(d0), "+f"(d1), "+f"(d2), "+f"(d3)
        : "r"(a0), "r"(a1), "r"(a2), "r"(a3), "r"(b0), "r"(b1));
}

__device__ __forceinline__ void ldsm_x4(uint32_t& r0, uint32_t& r1, uint32_t& r2, uint32_t& r3,
                                        uint32_t addr) {
    asm volatile("ldmatrix.sync.aligned.m8n8.x4.shared.b16 {%0,%1,%2,%3}, [%4];"
                 : "=r"(r0), "=r"(r1), "=r"(r2), "=r"(r3) : "r"(addr));
}
__device__ __forceinline__ void ldsm_x4_trans(uint32_t& r0, uint32_t& r1, uint32_t& r2, uint32_t& r3,
                                              uint32_t addr) {
    asm volatile("ldmatrix.sync.aligned.m8n8.x4.trans.shared.b16 {%0,%1,%2,%3}, [%4];"
                 : "=r"(r0), "=r"(r1), "=r"(r2), "=r"(r3) : "r"(addr));
}

__device__ __forceinline__ void cp_async16(uint32_t dst, const void* src) {
    asm volatile("cp.async.cg.shared.global [%0], [%1], 16;" :: "r"(dst), "l"(src));
}
#define CP_COMMIT() asm volatile("cp.async.commit_group;")

// ---------------------------------------------------------------------------
// Combined prep: blocks [0,4096): transpose+convert the 4 weights;
// blocks [4096,6144): x -> f16 (4 float4 per thread).
// ---------------------------------------------------------------------------
__global__ __launch_bounds__(256)
void prep_all(const float* __restrict__ x,
              const float* __restrict__ W0, const float* __restrict__ W1,
              const float* __restrict__ W2, const float* __restrict__ W3,
              __half* __restrict__ Whbase, __half* __restrict__ xh)
{
    __shared__ float t[32][33];
    const int bid = blockIdx.x;
    if (bid < 4096) {
        const int wz = bid >> 10;
        const int rem = bid & 1023;
        const int bx = (rem & 31) * 32;
        const int by = (rem >> 5) * 32;
        const float* in = (wz == 0) ? W0 : (wz == 1) ? W1 : (wz == 2) ? W2 : W3;
        __half* out = Whbase + (size_t)wz * DD * DD;
        const int tx = threadIdx.x & 31, ty = threadIdx.x >> 5;
#pragma unroll
        for (int i = 0; i < 4; i++) {
            int k = by + ty + i*8;
            t[ty + i*8][tx] = in[(size_t)k*DD + bx + tx];
        }
        __syncthreads();
#pragma unroll
        for (int i = 0; i < 4; i++) {
            int n = bx + ty + i*8;
            out[(size_t)n*DD + by + tx] = __float2half_rn(t[tx][ty + i*8]);
        }
    } else {
        const int b2 = bid - 4096;           // 0..2047
        const float4* in = (const float4*)x;
        uint2* out = (uint2*)xh;
#pragma unroll
        for (int j = 0; j < 4; j++) {
            int i = b2*1024 + j*256 + threadIdx.x;
            float4 v = in[i];
            uint2 o;
            o.x = packh2(v.x, v.y);
            o.y = packh2(v.z, v.w);
            out[i] = o;
        }
    }
}

// ---------------------------------------------------------------------------
// F16 tensor-core GEMM (QKV): CTA 128 threads (4 warps), tile 128x128.
// Fused N=3072 -> Q,K,V all [b,h,s,d] f16.
// ---------------------------------------------------------------------------
#define GSW 20                      // row stride in words
#define G_ROW_B (GSW*4)             // 80 bytes
#define G_A_B (128*G_ROW_B)         // 10240 bytes
#define G_B_B (128*G_ROW_B)         // 10240 bytes
#define G_STAGE_B (G_A_B + G_B_B)   // 20480 bytes
#define GEMM_SMEM (3*G_STAGE_B)     // 61440 bytes

__global__ __launch_bounds__(128, 2)
void gemm_qkv(const __half* __restrict__ A, const __half* __restrict__ WT,
              const float* __restrict__ bq, const float* __restrict__ bk,
              const float* __restrict__ bv,
              __half* __restrict__ Qo, __half* __restrict__ Ko,
              __half* __restrict__ Vo)
{
    extern __shared__ uint8_t smraw[];
    const uint32_t smem_b = (uint32_t)__cvta_generic_to_shared(smraw);

    const int tid  = threadIdx.x;
    const int lane = tid & 31;
    const int w    = tid >> 5;    // 0..3
    const int g    = lane >> 2;
    const int t4   = lane & 3;

    const int m0 = blockIdx.y * 128;
    const int n0 = blockIdx.x * 128;
    const int nk = KDIM / 32;     // 32

    const uint32_t a_off = (uint32_t)(w*32 + (lane & 15)) * G_ROW_B
                         + (uint32_t)(lane >> 4) * 16;
    const uint32_t b_off = (uint32_t)(((lane >> 4) << 3) + (lane & 7)) * G_ROW_B
                         + (uint32_t)((lane >> 3) & 1) * 16;

    auto issue = [&](int kb, int stg) {
        const uint32_t base = smem_b + stg * G_STAGE_B;
#pragma unroll
        for (int i = 0; i < 4; i++) {
            int c = tid + i*128;
            int row = c >> 2, c4 = c & 3;
            cp_async16(base + row*G_ROW_B + c4*16,
                       A + (size_t)(m0 + row)*KDIM + kb*32 + c4*8);
        }
#pragma unroll
        for (int i = 0; i < 4; i++) {
            int c = tid + i*128;
            int row = c >> 2, c4 = c & 3;
            cp_async16(base + G_A_B + row*G_ROW_B + c4*16,
                       WT + (size_t)(n0 + row)*KDIM + kb*32 + c4*8);
        }
        CP_COMMIT();
    };

    issue(0, 0);
    issue(1, 1);

    float acc[2][16][4];
#pragma unroll
    for (int mi = 0; mi < 2; mi++)
#pragma unroll
        for (int ni = 0; ni < 16; ni++)
#pragma unroll
            for (int r = 0; r < 4; r++) acc[mi][ni][r] = 0.f;

    for (int kb = 0; kb < nk; ++kb) {
        if (kb + 2 < nk) asm volatile("cp.async.wait_group 1;");
        else             asm volatile("cp.async.wait_group 0;");
        __syncthreads();
        if (kb + 2 < nk) issue(kb + 2, (kb + 2) % 3);

        const uint32_t As_b = smem_b + (kb % 3) * G_STAGE_B;
        const uint32_t Bs_b = As_b + G_A_B;

#pragma unroll
        for (int ks = 0; ks < 2; ++ks) {
            uint32_t au[2][4], bu[16][2];
#pragma unroll
            for (int mi = 0; mi < 2; mi++)
                ldsm_x4(au[mi][0], au[mi][1], au[mi][2], au[mi][3],
                        As_b + a_off + mi*(16*G_ROW_B) + ks*32);
#pragma unroll
            for (int p = 0; p < 8; p++)
                ldsm_x4(bu[2*p][0], bu[2*p][1], bu[2*p+1][0], bu[2*p+1][1],
                        Bs_b + b_off + p*(16*G_ROW_B) + ks*32);
#pragma unroll
            for (int mi = 0; mi < 2; mi++)
#pragma unroll
                for (int ni = 0; ni < 16; ni++)
                    mma_f16(acc[mi][ni][0], acc[mi][ni][1], acc[mi][ni][2], acc[mi][ni][3],
                            au[mi][0], au[mi][1], au[mi][2], au[mi][3],
                            bu[ni][0], bu[ni][1]);
        }
    }

    const int widx = n0 >> 10;
    const float* bias = (widx == 0) ? bq : (widx == 1) ? bk : bv;
    __half* C = (widx == 0) ? Qo : (widx == 1) ? Ko : Vo;
#pragma unroll
    for (int mi = 0; mi < 2; mi++) {
#pragma unroll
        for (int ni = 0; ni < 16; ni++) {
            const int n = n0 + ni*8 + 2*t4;
            const int nl = n & (DD - 1);
            float2 bia = *(const float2*)&bias[nl];
            const int mg = m0 + w*32 + mi*16 + g;
            float v00 = acc[mi][ni][0] + bia.x, v01 = acc[mi][ni][1] + bia.y;
            float v10 = acc[mi][ni][2] + bia.x, v11 = acc[mi][ni][3] + bia.y;
            int h = nl >> 6, d = nl & 63;
            int b0 = mg >> 11, s0 = mg & (SS-1);
            *(uint32_t*)&C[(((size_t)(b0*HH + h)*SS + s0) << 6) + d] = packh2(v00, v01);
            int b1 = (mg+8) >> 11, s1 = (mg+8) & (SS-1);
            *(uint32_t*)&C[(((size_t)(b1*HH + h)*SS + s1) << 6) + d] = packh2(v10, v11);
        }
    }
}

// ---------------------------------------------------------------------------
// Wo GEMM: tile 64x128, warp = 16 m-rows x 128 n-cols, 3 CTAs/SM.
// Grid (8,128) = 1024 CTAs -> 2.31 waves at 444 resident (vs 1.73 @ 512).
// fp32 output + bias. Same per-output MMA order as before (bit-identical).
// ---------------------------------------------------------------------------
#define W_A_B (64*G_ROW_B)          // 5120 bytes
#define W_STAGE_B (W_A_B + G_B_B)   // 15360 bytes
#define WO_SMEM (3*W_STAGE_B)       // 46080 bytes

__global__ __launch_bounds__(128, 3)
void gemm_wo(const __half* __restrict__ A, const __half* __restrict__ WT,
             const float* __restrict__ bias, float* __restrict__ Fo)
{
    extern __shared__ uint8_t smraw[];
    const uint32_t smem_b = (uint32_t)__cvta_generic_to_shared(smraw);

    const int tid  = threadIdx.x;
    const int lane = tid & 31;
    const int w    = tid >> 5;    // 0..3
    const int g    = lane >> 2;
    const int t4   = lane & 3;

    const int m0 = blockIdx.y * 64;
    const int n0 = blockIdx.x * 128;
    const int nk = KDIM / 32;     // 32

    const uint32_t a_off = (uint32_t)(w*16 + (lane & 15)) * G_ROW_B
                         + (uint32_t)(lane >> 4) * 16;
    const uint32_t b_off = (uint32_t)(((lane >> 4) << 3) + (lane & 7)) * G_ROW_B
                         + (uint32_t)((lane >> 3) & 1) * 16;

    auto issue = [&](int kb, int stg) {
        const uint32_t base = smem_b + stg * W_STAGE_B;
#pragma unroll
        for (int i = 0; i < 2; i++) {
            int c = tid + i*128;              // 0..255 : A 64 rows x 4 chunks
            int row = c >> 2, c4 = c & 3;
            cp_async16(base + row*G_ROW_B + c4*16,
                       A + (size_t)(m0 + row)*KDIM + kb*32 + c4*8);
        }
#pragma unroll
        for (int i = 0; i < 4; i++) {
            int c = tid + i*128;              // 0..511 : B 128 rows x 4 chunks
            int row = c >> 2, c4 = c & 3;
            cp_async16(base + W_A_B + row*G_ROW_B + c4*16,
                       WT + (size_t)(n0 + row)*KDIM + kb*32 + c4*8);
        }
        CP_COMMIT();
    };

    issue(0, 0);
    issue(1, 1);

    float acc[16][4];
#pragma unroll
    for (int ni = 0; ni < 16; ni++)
#pragma unroll
        for (int r = 0; r < 4; r++) acc[ni][r] = 0.f;

    for (int kb = 0; kb < nk; ++kb) {
        if (kb + 2 < nk) asm volatile("cp.async.wait_group 1;");
        else             asm volatile("cp.async.wait_group 0;");
        __syncthreads();
        if (kb + 2 < nk) issue(kb + 2, (kb + 2) % 3);

        const uint32_t As_b = smem_b + (kb % 3) * W_STAGE_B;
        const uint32_t Bs_b = As_b + W_A_B;

#pragma unroll
        for (int ks = 0; ks < 2; ++ks) {
            uint32_t au[4], bu[16][2];
            ldsm_x4(au[0], au[1], au[2], au[3], As_b + a_off + ks*32);
#pragma unroll
            for (int p = 0; p < 8; p++)
                ldsm_x4(bu[2*p][0], bu[2*p][1], bu[2*p+1][0], bu[2*p+1][1],
                        Bs_b + b_off + p*(16*G_ROW_B) + ks*32);
#pragma unroll
            for (int ni = 0; ni < 16; ni++)
                mma_f16(acc[ni][0], acc[ni][1], acc[ni][2], acc[ni][3],
                        au[0], au[1], au[2], au[3], bu[ni][0], bu[ni][1]);
        }
    }

#pragma unroll
    for (int ni = 0; ni < 16; ni++) {
        const int n = n0 + ni*8 + 2*t4;
        float2 bia = *(const float2*)&bias[n];
        const int mg = m0 + w*16 + g;
        *(float2*)&Fo[(size_t)mg * DD + n] =
            make_float2(acc[ni][0] + bia.x, acc[ni][1] + bia.y);
        *(float2*)&Fo[(size_t)(mg+8) * DD + n] =
            make_float2(acc[ni][2] + bia.x, acc[ni][3] + bia.y);
    }
}

// ---------------------------------------------------------------------------
// F16 flash attention, estimated-max softmax, V via ldmatrix.trans. (R14)
// ---------------------------------------------------------------------------
#define AKV_ROW_B 144                   // 72 halves * 2
#define AKV_TILE_B (64*AKV_ROW_B)       // 9216
#define ATT_STAGE_B (2*AKV_TILE_B)      // 18432
#define ATT_SMEM (2*ATT_STAGE_B)

__global__ __launch_bounds__(128, 2)
void attn_h5(const __half* __restrict__ Q, const __half* __restrict__ K,
             const __half* __restrict__ V, __half* __restrict__ ctx)
{
    extern __shared__ uint32_t smu[];
    const uint32_t smem_b = (uint32_t)__cvta_generic_to_shared(smu);

    const int tid  = threadIdx.x;
    const int lane = tid & 31;
    const int w    = tid >> 5;
    const int g    = lane >> 2;
    const int t4   = lane & 3;

    const int b  = blockIdx.z;
    const int h  = blockIdx.y;
    const int q0 = blockIdx.x * 128;
    const size_t head_off = (size_t)(b * HH + h) * SS * DK;    // Q,K,V [s][d]

    const uint32_t k_off = (uint32_t)(((lane >> 4) << 3) + (lane & 7)) * AKV_ROW_B
                         + (uint32_t)((lane >> 3) & 1) * 16;
    const uint32_t v_off = (uint32_t)(((lane >> 3) & 1) * 8 + (lane & 7)) * AKV_ROW_B
                         + (uint32_t)(lane >> 4) * 16;

    auto issueKV = [&](int t, int stg) {
        const __half* Kt = K + head_off + ((size_t)t << 12);   // t*64*64
        const __half* Vt = V + head_off + ((size_t)t << 12);
        const uint32_t base = smem_b + stg * ATT_STAGE_B;
#pragma unroll
        for (int i = 0; i < 4; i++) {
            int c = tid + (i << 7);
            int row = c >> 3, c8 = c & 7;
            cp_async16(base + row*AKV_ROW_B + c8*16, Kt + (row << 6) + c8*8);
            cp_async16(base + AKV_TILE_B + row*AKV_ROW_B + c8*16, Vt + (row << 6) + c8*8);
        }
        CP_COMMIT();
    };

    issueKV(0, 0);

    const __half2 qs = __float2half2_rn(0.125f * LOG2E);
    uint32_t qa[2][4][4];
    {
        const __half* Qb = Q + head_off + (size_t)(q0 + w*32) * DK;
#pragma unroll
        for (int mi = 0; mi < 2; mi++) {
            const __half* Qm = Qb + (size_t)(mi*16) * DK;
#pragma unroll
            for (int ks = 0; ks < 4; ks++) {
                __half2 p0 = __hmul2(*(const __half2*)&Qm[(size_t)g     *DK + ks*16 + 2*t4    ], qs);
                __half2 p1 = __hmul2(*(const __half2*)&Qm[(size_t)(g+8) *DK + ks*16 + 2*t4    ], qs);
                __half2 p2 = __hmul2(*(const __half2*)&Qm[(size_t)g     *DK + ks*16 + 2*t4 + 8], qs);
                __half2 p3 = __hmul2(*(const __half2*)&Qm[(size_t)(g+8) *DK + ks*16 + 2*t4 + 8], qs);
                qa[mi][ks][0] = *(uint32_t*)&p0;
                qa[mi][ks][1] = *(uint32_t*)&p1;
                qa[mi][ks][2] = *(uint32_t*)&p2;
                qa[mi][ks][3] = *(uint32_t*)&p3;
            }
        }
    }

    float o[2][8][4];
#pragma unroll
    for (int mi = 0; mi < 2; mi++)
#pragma unroll
        for (int ni = 0; ni < 8; ni++)
#pragma unroll
            for (int r = 0; r < 4; r++) o[mi][ni][r] = 0.f;
    float la[2][4] = {{0.f,0.f,0.f,0.f},{0.f,0.f,0.f,0.f}};
    float mest[2][2];

    for (int t = 0; t < SS / 64; ++t) {
        asm volatile("cp.async.wait_group 0;");
        __syncthreads();
        if (t + 1 < SS / 64) issueKV(t + 1, (t + 1) & 1);

        const uint32_t Kst_b = smem_b + (t & 1) * ATT_STAGE_B;
        const uint32_t Vst_b = Kst_b + AKV_TILE_B;

        float s[2][8][4];
#pragma unroll
        for (int mi = 0; mi < 2; mi++)
#pragma unroll
            for (int ni = 0; ni < 8; ni++)
#pragma unroll
                for (int r = 0; r < 4; r++) s[mi][ni][r] = 0.f;
#pragma unroll
        for (int ks = 0; ks < 4; ks++) {
            uint32_t bu[8][2];
#pragma unroll
            for (int p = 0; p < 4; p++)
                ldsm_x4(bu[2*p][0], bu[2*p][1], bu[2*p+1][0], bu[2*p+1][1],
                        Kst_b + k_off + p*(16*AKV_ROW_B) + ks*32);
#pragma unroll
            for (int ni = 0; ni < 8; ni++) {
                mma_f16(s[0][ni][0], s[0][ni][1], s[0][ni][2], s[0][ni][3],
                        qa[0][ks][0], qa[0][ks][1], qa[0][ks][2], qa[0][ks][3],
                        bu[ni][0], bu[ni][1]);
                mma_f16(s[1][ni][0], s[1][ni][1], s[1][ni][2], s[1][ni][3],
                        qa[1][ks][0], qa[1][ks][1], qa[1][ks][2], qa[1][ks][3],
                        bu[ni][0], bu[ni][1]);
            }
        }

        if (t == 0) {
#pragma unroll
            for (int mi = 0; mi < 2; mi++) {
                float mx0 = -CUDART_INF_F, mx1 = -CUDART_INF_F;
#pragma unroll
                for (int ni = 0; ni < 8; ni++) {
                    mx0 = fmaxf(mx0, fmaxf(s[mi][ni][0], s[mi][ni][1]));
                    mx1 = fmaxf(mx1, fmaxf(s[mi][ni][2], s[mi][ni][3]));
                }
                mx0 = fmaxf(mx0, __shfl_xor_sync(0xffffffffu, mx0, 1));
                mx0 = fmaxf(mx0, __shfl_xor_sync(0xffffffffu, mx0, 2));
                mx1 = fmaxf(mx1, __shfl_xor_sync(0xffffffffu, mx1, 1));
                mx1 = fmaxf(mx1, __shfl_xor_sync(0xffffffffu, mx1, 2));
                mest[mi][0] = mx0;
                mest[mi][1] = mx1;
            }
        }

        uint32_t e[2][8][2];
#pragma unroll
        for (int mi = 0; mi < 2; mi++) {
            const float m0f = mest[mi][0], m1f = mest[mi][1];
#pragma unroll
            for (int ni = 0; ni < 8; ni++) {
                e[mi][ni][0] = ex2h2(packh2(s[mi][ni][0] - m0f, s[mi][ni][1] - m0f));
                e[mi][ni][1] = ex2h2(packh2(s[mi][ni][2] - m1f, s[mi][ni][3] - m1f));
            }
        }

#pragma unroll
        for (int ks = 0; ks < 4; ks++) {
            uint32_t vu[8][2];
#pragma unroll
            for (int p = 0; p < 4; p++)
                ldsm_x4_trans(vu[2*p][0], vu[2*p][1], vu[2*p+1][0], vu[2*p+1][1],
                              Vst_b + v_off + ks*(16*AKV_ROW_B) + p*32);
            const uint32_t pa00 = e[0][2*ks][0], pa01 = e[0][2*ks][1];
            const uint32_t pa02 = e[0][2*ks+1][0], pa03 = e[0][2*ks+1][1];
            const uint32_t pa10 = e[1][2*ks][0], pa11 = e[1][2*ks][1];
            const uint32_t pa12 = e[1][2*ks+1][0], pa13 = e[1][2*ks+1][1];
#pragma unroll
            for (int ni = 0; ni < 8; ni++) {
                mma_f16(o[0][ni][0], o[0][ni][1], o[0][ni][2], o[0][ni][3],
                        pa00, pa01, pa02, pa03, vu[ni][0], vu[ni][1]);
                mma_f16(o[1][ni][0], o[1][ni][1], o[1][ni][2], o[1][ni][3],
                        pa10, pa11, pa12, pa13, vu[ni][0], vu[ni][1]);
            }
            mma_f16(la[0][0], la[0][1], la[0][2], la[0][3],
                    pa00, pa01, pa02, pa03, ONES_H2, ONES_H2);
            mma_f16(la[1][0], la[1][1], la[1][2], la[1][3],
                    pa10, pa11, pa12, pa13, ONES_H2, ONES_H2);
        }
    }

#pragma unroll
    for (int mi = 0; mi < 2; mi++) {
        float inv0 = 1.f / la[mi][0], inv1 = 1.f / la[mi][2];
        const int q_r0 = q0 + w*32 + mi*16 + g;
#pragma unroll
        for (int ni = 0; ni < 8; ni++) {
            const int d = h*64 + ni*8 + 2*t4;
            *(uint32_t*)&ctx[(size_t)(b * SS + q_r0    ) * DD + d] =
                packh2(o[mi][ni][0]*inv0, o[mi][ni][1]*inv0);
            *(uint32_t*)&ctx[(size_t)(b * SS + q_r0 + 8) * DD + d] =
                packh2(o[mi][ni][2]*inv1, o[mi][ni][3]*inv1);
        }
    }
}

// ---------------------------------------------------------------------------
extern "C" void kernel_launch(void* const* d_in, const int* in_sizes, int n_in,
                              void* d_out, int out_size)
{
    const float* x  = (const float*)d_in[0];
    const float* Wq = (const float*)d_in[1];
    const float* bq = (const float*)d_in[2];
    const float* Wk = (const float*)d_in[3];
    const float* bk = (const float*)d_in[4];
    const float* Wv = (const float*)d_in[5];
    const float* bv = (const float*)d_in[6];
    const float* Wo = (const float*)d_in[7];
    const float* bo = (const float*)d_in[8];
    float* out = (float*)d_out;

    __half *xh, *Wh, *Qh, *Kh, *Vh, *ctxh;
    cudaGetSymbolAddress((void**)&xh,   g_xh);
    cudaGetSymbolAddress((void**)&Wh,   g_Wh);
    cudaGetSymbolAddress((void**)&Qh,   g_Qh);
    cudaGetSymbolAddress((void**)&Kh,   g_Kh);
    cudaGetSymbolAddress((void**)&Vh,   g_Vh);
    cudaGetSymbolAddress((void**)&ctxh, g_ctxh);
    __half* Wh3 = Wh + 3*(size_t)DD*DD;

    // Prep: W transpose+convert and x->f16 in ONE launch
    prep_all<<<6144, 256>>>(x, Wq, Wk, Wv, Wo, Wh, xh);

    cudaFuncSetAttribute((const void*)gemm_qkv,
                         cudaFuncAttributeMaxDynamicSharedMemorySize, GEMM_SMEM);
    cudaFuncSetAttribute((const void*)gemm_wo,
                         cudaFuncAttributeMaxDynamicSharedMemorySize, WO_SMEM);
    cudaFuncSetAttribute((const void*)attn_h5,
                         cudaFuncAttributeMaxDynamicSharedMemorySize, ATT_SMEM);

    // Fused QKV projection: N = 3072 (Wq|Wk|Wv contiguous in g_Wh)
    gemm_qkv<<<dim3(3*DD/128, MM/128), 128, GEMM_SMEM>>>(
        xh, Wh, bq, bk, bv, Qh, Kh, Vh);

    attn_h5<<<dim3(SS / 128, HH, BB), 128, ATT_SMEM>>>(Qh, Kh, Vh, ctxh);

    // Output projection: 64x128 tiles, 3 CTAs/SM, 1024 CTAs
    gemm_wo<<<dim3(DD/128, MM/64), 128, WO_SMEM>>>(ctxh, Wh3, bo, out);
}

// round 17
// speedup vs baseline: 1.0351x; 1.0351x over previous
#include <cuda_runtime.h>
#include <cuda_fp16.h>
#include <math_constants.h>
#include <cstdint>

// Problem constants
#define BB 4
#define SS 2048
#define DD 1024
#define HH 16
#define DK 64
#define MM (BB*SS)          // 8192 rows
#define KDIM 1024

// Scratch in device globals (no allocation allowed)
__device__ __half g_xh[MM*DD];           // f16 x (row-major)
__device__ __half g_Wh[4][DD*DD];        // f16 TRANSPOSED weights [n][k] (q,k,v,o)
__device__ __half g_Qh[BB*HH*SS*DK];     // [b,h,s,d]
__device__ __half g_Kh[BB*HH*SS*DK];     // [b,h,s,d]
__device__ __half g_Vh[BB*HH*SS*DK];     // [b,h,s,d]  (PV uses ldmatrix.trans)
__device__ __half g_ctxh[BB*SS*DD];      // f16 ctx

#define ONES_H2 0x3C003C00u
#define LOG2E 1.4426950408889634f

__device__ __forceinline__ uint32_t packh2(float lo, float hi) {
    __half2 h = __float22half2_rn(make_float2(lo, hi));
    return *(uint32_t*)&h;
}
__device__ __forceinline__ uint32_t ex2h2(uint32_t a) {
    uint32_t d;
    asm("ex2.approx.f16x2 %0, %1;" : "=r"(d) : "r"(a));
    return d;
}

__device__ __forceinline__ void mma_f16(float& d0, float& d1, float& d2, float& d3,
                                        uint32_t a0, uint32_t a1, uint32_t a2, uint32_t a3,
                                        uint32_t b0, uint32_t b1) {
    asm volatile(
        "mma.sync.aligned.m16n8k16.row.col.f32.f16.f16.f32 "
        "{%0,%1,%2,%3}, {%4,%5,%6,%7}, {%8,%9}, {%0,%1,%2,%3};"
        : "+f"(d0), "+f"(d1), "+f"(d2), "+f"(d3)
        : "r"(a0), "r"(a1), "r"(a2), "r"(a3), "r"(b0), "r"(b1));
}

__device__ __forceinline__ void ldsm_x4(uint32_t& r0, uint32_t& r1, uint32_t& r2, uint32_t& r3,
                                        uint32_t addr) {
    asm volatile("ldmatrix.sync.aligned.m8n8.x4.shared.b16 {%0,%1,%2,%3}, [%4];"
                 : "=r"(r0), "=r"(r1), "=r"(r2), "=r"(r3) : "r"(addr));
}
__device__ __forceinline__ void ldsm_x4_trans(uint32_t& r0, uint32_t& r1, uint32_t& r2, uint32_t& r3,
                                              uint32_t addr) {
    asm volatile("ldmatrix.sync.aligned.m8n8.x4.trans.shared.b16 {%0,%1,%2,%3}, [%4];"
                 : "=r"(r0), "=r"(r1), "=r"(r2), "=r"(r3) : "r"(addr));
}

__device__ __forceinline__ void cp_async16(uint32_t dst, const void* src) {
    asm volatile("cp.async.cg.shared.global [%0], [%1], 16;" :: "r"(dst), "l"(src));
}
#define CP_COMMIT() asm volatile("cp.async.commit_group;")

// ---------------------------------------------------------------------------
// Combined prep: blocks [0,4096): transpose+convert the 4 weights;
// blocks [4096,6144): x -> f16.
// ---------------------------------------------------------------------------
__global__ __launch_bounds__(256)
void prep_all(const float* __restrict__ x,
              const float* __restrict__ W0, const float* __restrict__ W1,
              const float* __restrict__ W2, const float* __restrict__ W3,
              __half* __restrict__ Whbase, __half* __restrict__ xh)
{
    __shared__ float t[32][33];
    const int bid = blockIdx.x;
    if (bid < 4096) {
        const int wz = bid >> 10;
        const int rem = bid & 1023;
        const int bx = (rem & 31) * 32;
        const int by = (rem >> 5) * 32;
        const float* in = (wz == 0) ? W0 : (wz == 1) ? W1 : (wz == 2) ? W2 : W3;
        __half* out = Whbase + (size_t)wz * DD * DD;
        const int tx = threadIdx.x & 31, ty = threadIdx.x >> 5;
#pragma unroll
        for (int i = 0; i < 4; i++) {
            int k = by + ty + i*8;
            t[ty + i*8][tx] = in[(size_t)k*DD + bx + tx];
        }
        __syncthreads();
#pragma unroll
        for (int i = 0; i < 4; i++) {
            int n = bx + ty + i*8;
            out[(size_t)n*DD + by + tx] = __float2half_rn(t[tx][ty + i*8]);
        }
    } else {
        const int b2 = bid - 4096;           // 0..2047
        const float4* in = (const float4*)x;
        uint2* out = (uint2*)xh;
#pragma unroll
        for (int j = 0; j < 4; j++) {
            int i = b2*1024 + j*256 + threadIdx.x;
            float4 v = in[i];
            uint2 o;
            o.x = packh2(v.x, v.y);
            o.y = packh2(v.z, v.w);
            out[i] = o;
        }
    }
}

// ---------------------------------------------------------------------------
// F16 tensor-core GEMM: CTA 128 threads (4 warps), tile 128x128. (R14 shape)
// QKV=true: fused N=3072 -> Q,K,V [b,h,s,d] f16. QKV=false: fp32 out + bias.
// ---------------------------------------------------------------------------
#define GSW 20                      // row stride in words
#define G_ROW_B (GSW*4)             // 80 bytes
#define G_A_B (128*G_ROW_B)         // 10240 bytes
#define G_B_B (128*G_ROW_B)         // 10240 bytes
#define G_STAGE_B (G_A_B + G_B_B)   // 20480 bytes
#define GEMM_SMEM (3*G_STAGE_B)     // 61440 bytes

template<bool QKV>
__global__ __launch_bounds__(128, 2)
void gemm_big(const __half* __restrict__ A, const __half* __restrict__ WT,
              const float* __restrict__ bq, const float* __restrict__ bk,
              const float* __restrict__ bv,
              __half* __restrict__ Qo, __half* __restrict__ Ko,
              __half* __restrict__ Vo, float* __restrict__ Fo)
{
    extern __shared__ uint8_t smraw[];
    const uint32_t smem_b = (uint32_t)__cvta_generic_to_shared(smraw);

    const int tid  = threadIdx.x;
    const int lane = tid & 31;
    const int w    = tid >> 5;    // 0..3
    const int g    = lane >> 2;
    const int t4   = lane & 3;

    const int m0 = blockIdx.y * 128;
    const int n0 = blockIdx.x * 128;
    const int nk = KDIM / 32;     // 32

    const uint32_t a_off = (uint32_t)(w*32 + (lane & 15)) * G_ROW_B
                         + (uint32_t)(lane >> 4) * 16;
    const uint32_t b_off = (uint32_t)(((lane >> 4) << 3) + (lane & 7)) * G_ROW_B
                         + (uint32_t)((lane >> 3) & 1) * 16;

    auto issue = [&](int kb, int stg) {
        const uint32_t base = smem_b + stg * G_STAGE_B;
#pragma unroll
        for (int i = 0; i < 4; i++) {
            int c = tid + i*128;
            int row = c >> 2, c4 = c & 3;
            cp_async16(base + row*G_ROW_B + c4*16,
                       A + (size_t)(m0 + row)*KDIM + kb*32 + c4*8);
        }
#pragma unroll
        for (int i = 0; i < 4; i++) {
            int c = tid + i*128;
            int row = c >> 2, c4 = c & 3;
            cp_async16(base + G_A_B + row*G_ROW_B + c4*16,
                       WT + (size_t)(n0 + row)*KDIM + kb*32 + c4*8);
        }
        CP_COMMIT();
    };

    issue(0, 0);
    issue(1, 1);

    float acc[2][16][4];
#pragma unroll
    for (int mi = 0; mi < 2; mi++)
#pragma unroll
        for (int ni = 0; ni < 16; ni++)
#pragma unroll
            for (int r = 0; r < 4; r++) acc[mi][ni][r] = 0.f;

    for (int kb = 0; kb < nk; ++kb) {
        if (kb + 2 < nk) asm volatile("cp.async.wait_group 1;");
        else             asm volatile("cp.async.wait_group 0;");
        __syncthreads();
        if (kb + 2 < nk) issue(kb + 2, (kb + 2) % 3);

        const uint32_t As_b = smem_b + (kb % 3) * G_STAGE_B;
        const uint32_t Bs_b = As_b + G_A_B;

#pragma unroll
        for (int ks = 0; ks < 2; ++ks) {
            uint32_t au[2][4], bu[16][2];
#pragma unroll
            for (int mi = 0; mi < 2; mi++)
                ldsm_x4(au[mi][0], au[mi][1], au[mi][2], au[mi][3],
                        As_b + a_off + mi*(16*G_ROW_B) + ks*32);
#pragma unroll
            for (int p = 0; p < 8; p++)
                ldsm_x4(bu[2*p][0], bu[2*p][1], bu[2*p+1][0], bu[2*p+1][1],
                        Bs_b + b_off + p*(16*G_ROW_B) + ks*32);
#pragma unroll
            for (int mi = 0; mi < 2; mi++)
#pragma unroll
                for (int ni = 0; ni < 16; ni++)
                    mma_f16(acc[mi][ni][0], acc[mi][ni][1], acc[mi][ni][2], acc[mi][ni][3],
                            au[mi][0], au[mi][1], au[mi][2], au[mi][3],
                            bu[ni][0], bu[ni][1]);
        }
    }

    const int widx = QKV ? (n0 >> 10) : 3;
    const float* bias = QKV ? (widx == 0 ? bq : widx == 1 ? bk : bv) : bq;
#pragma unroll
    for (int mi = 0; mi < 2; mi++) {
#pragma unroll
        for (int ni = 0; ni < 16; ni++) {
            const int n = n0 + ni*8 + 2*t4;
            const int nl = n & (DD - 1);
            float2 bia = *(const float2*)&bias[QKV ? nl : n];
            const int mg = m0 + w*32 + mi*16 + g;
            float v00 = acc[mi][ni][0] + bia.x, v01 = acc[mi][ni][1] + bia.y;
            float v10 = acc[mi][ni][2] + bia.x, v11 = acc[mi][ni][3] + bia.y;
            if (!QKV) {
                *(float2*)&Fo[(size_t)mg * DD + n]      = make_float2(v00, v01);
                *(float2*)&Fo[(size_t)(mg+8) * DD + n]  = make_float2(v10, v11);
            } else {
                __half* C = (widx == 0) ? Qo : (widx == 1) ? Ko : Vo;
                int h = nl >> 6, d = nl & 63;
                int b0 = mg >> 11, s0 = mg & (SS-1);
                *(uint32_t*)&C[(((size_t)(b0*HH + h)*SS + s0) << 6) + d] = packh2(v00, v01);
                int b1 = (mg+8) >> 11, s1 = (mg+8) & (SS-1);
                *(uint32_t*)&C[(((size_t)(b1*HH + h)*SS + s1) << 6) + d] = packh2(v10, v11);
            }
        }
    }
}

// ---------------------------------------------------------------------------
// F16 flash attention, estimated-max softmax, V via ldmatrix.trans.
// 128 KV rows loaded per cp.async group (2 sub-tiles of 64), ONE barrier +
// wait_group per 128 rows (half the sync count of R14). Arithmetic identical.
// Stage layout: [K0][K1][V0][V1], 9216 B each.
// ---------------------------------------------------------------------------
#define AKV_ROW_B 144                   // 72 halves * 2
#define AKV_TILE_B (64*AKV_ROW_B)       // 9216
#define ATT_STAGE_B (4*AKV_TILE_B)      // 36864
#define ATT_SMEM (2*ATT_STAGE_B)        // 73728

__global__ __launch_bounds__(128, 2)
void attn_h6(const __half* __restrict__ Q, const __half* __restrict__ K,
             const __half* __restrict__ V, __half* __restrict__ ctx)
{
    extern __shared__ uint32_t smu[];
    const uint32_t smem_b = (uint32_t)__cvta_generic_to_shared(smu);

    const int tid  = threadIdx.x;
    const int lane = tid & 31;
    const int w    = tid >> 5;
    const int g    = lane >> 2;
    const int t4   = lane & 3;

    const int b  = blockIdx.z;
    const int h  = blockIdx.y;
    const int q0 = blockIdx.x * 128;
    const size_t head_off = (size_t)(b * HH + h) * SS * DK;    // Q,K,V [s][d]

    const uint32_t k_off = (uint32_t)(((lane >> 4) << 3) + (lane & 7)) * AKV_ROW_B
                         + (uint32_t)((lane >> 3) & 1) * 16;
    const uint32_t v_off = (uint32_t)(((lane >> 3) & 1) * 8 + (lane & 7)) * AKV_ROW_B
                         + (uint32_t)(lane >> 4) * 16;

    // Load 128 KV rows (tiles 2*tt and 2*tt+1) into stage stg.
    auto issueKV = [&](int tt, int stg) {
        const uint32_t base = smem_b + stg * ATT_STAGE_B;
#pragma unroll
        for (int j = 0; j < 2; j++) {
            const __half* Kt = K + head_off + ((size_t)(2*tt + j) << 12);
            const __half* Vt = V + head_off + ((size_t)(2*tt + j) << 12);
#pragma unroll
            for (int i = 0; i < 4; i++) {
                int c = tid + (i << 7);
                int row = c >> 3, c8 = c & 7;
                cp_async16(base + j*AKV_TILE_B + row*AKV_ROW_B + c8*16,
                           Kt + (row << 6) + c8*8);
                cp_async16(base + (2 + j)*AKV_TILE_B + row*AKV_ROW_B + c8*16,
                           Vt + (row << 6) + c8*8);
            }
        }
        CP_COMMIT();
    };

    issueKV(0, 0);

    // ---- Q fragments (persistent), scale = (1/8)*log2e folded in
    const __half2 qs = __float2half2_rn(0.125f * LOG2E);
    uint32_t qa[2][4][4];
    {
        const __half* Qb = Q + head_off + (size_t)(q0 + w*32) * DK;
#pragma unroll
        for (int mi = 0; mi < 2; mi++) {
            const __half* Qm = Qb + (size_t)(mi*16) * DK;
#pragma unroll
            for (int ks = 0; ks < 4; ks++) {
                __half2 p0 = __hmul2(*(const __half2*)&Qm[(size_t)g     *DK + ks*16 + 2*t4    ], qs);
                __half2 p1 = __hmul2(*(const __half2*)&Qm[(size_t)(g+8) *DK + ks*16 + 2*t4    ], qs);
                __half2 p2 = __hmul2(*(const __half2*)&Qm[(size_t)g     *DK + ks*16 + 2*t4 + 8], qs);
                __half2 p3 = __hmul2(*(const __half2*)&Qm[(size_t)(g+8) *DK + ks*16 + 2*t4 + 8], qs);
                qa[mi][ks][0] = *(uint32_t*)&p0;
                qa[mi][ks][1] = *(uint32_t*)&p1;
                qa[mi][ks][2] = *(uint32_t*)&p2;
                qa[mi][ks][3] = *(uint32_t*)&p3;
            }
        }
    }

    float o[2][8][4];
#pragma unroll
    for (int mi = 0; mi < 2; mi++)
#pragma unroll
        for (int ni = 0; ni < 8; ni++)
#pragma unroll
            for (int r = 0; r < 4; r++) o[mi][ni][r] = 0.f;
    float la[2][4] = {{0.f,0.f,0.f,0.f},{0.f,0.f,0.f,0.f}};
    float mest[2][2];

    for (int tt = 0; tt < SS / 128; ++tt) {
        asm volatile("cp.async.wait_group 0;");
        __syncthreads();
        if (tt + 1 < SS / 128) issueKV(tt + 1, (tt + 1) & 1);

        const uint32_t stage_b = smem_b + (tt & 1) * ATT_STAGE_B;

#pragma unroll
        for (int j = 0; j < 2; j++) {
            const uint32_t Kst_b = stage_b + j*AKV_TILE_B;
            const uint32_t Vst_b = stage_b + (2 + j)*AKV_TILE_B;

            // ---- S = Q @ K^T  (log2 domain)
            float s[2][8][4];
#pragma unroll
            for (int mi = 0; mi < 2; mi++)
#pragma unroll
                for (int ni = 0; ni < 8; ni++)
#pragma unroll
                    for (int r = 0; r < 4; r++) s[mi][ni][r] = 0.f;
#pragma unroll
            for (int ks = 0; ks < 4; ks++) {
                uint32_t bu[8][2];
#pragma unroll
                for (int p = 0; p < 4; p++)
                    ldsm_x4(bu[2*p][0], bu[2*p][1], bu[2*p+1][0], bu[2*p+1][1],
                            Kst_b + k_off + p*(16*AKV_ROW_B) + ks*32);
#pragma unroll
                for (int ni = 0; ni < 8; ni++) {
                    mma_f16(s[0][ni][0], s[0][ni][1], s[0][ni][2], s[0][ni][3],
                            qa[0][ks][0], qa[0][ks][1], qa[0][ks][2], qa[0][ks][3],
                            bu[ni][0], bu[ni][1]);
                    mma_f16(s[1][ni][0], s[1][ni][1], s[1][ni][2], s[1][ni][3],
                            qa[1][ks][0], qa[1][ks][1], qa[1][ks][2], qa[1][ks][3],
                            bu[ni][0], bu[ni][1]);
                }
            }

            // ---- estimate row max from the first sub-tile only
            if (tt == 0 && j == 0) {
#pragma unroll
                for (int mi = 0; mi < 2; mi++) {
                    float mx0 = -CUDART_INF_F, mx1 = -CUDART_INF_F;
#pragma unroll
                    for (int ni = 0; ni < 8; ni++) {
                        mx0 = fmaxf(mx0, fmaxf(s[mi][ni][0], s[mi][ni][1]));
                        mx1 = fmaxf(mx1, fmaxf(s[mi][ni][2], s[mi][ni][3]));
                    }
                    mx0 = fmaxf(mx0, __shfl_xor_sync(0xffffffffu, mx0, 1));
                    mx0 = fmaxf(mx0, __shfl_xor_sync(0xffffffffu, mx0, 2));
                    mx1 = fmaxf(mx1, __shfl_xor_sync(0xffffffffu, mx1, 1));
                    mx1 = fmaxf(mx1, __shfl_xor_sync(0xffffffffu, mx1, 2));
                    mest[mi][0] = mx0;
                    mest[mi][1] = mx1;
                }
            }

            // ---- p = 2^(s - m_est): fp32 subtract, pack, f16x2 ex2
            uint32_t e[2][8][2];
#pragma unroll
            for (int mi = 0; mi < 2; mi++) {
                const float m0f = mest[mi][0], m1f = mest[mi][1];
#pragma unroll
                for (int ni = 0; ni < 8; ni++) {
                    e[mi][ni][0] = ex2h2(packh2(s[mi][ni][0] - m0f, s[mi][ni][1] - m0f));
                    e[mi][ni][1] = ex2h2(packh2(s[mi][ni][2] - m1f, s[mi][ni][3] - m1f));
                }
            }

            // ---- O += P @ V (ldmatrix.trans) ; l += P @ ones
#pragma unroll
            for (int ks = 0; ks < 4; ks++) {
                uint32_t vu[8][2];
#pragma unroll
                for (int p = 0; p < 4; p++)
                    ldsm_x4_trans(vu[2*p][0], vu[2*p][1], vu[2*p+1][0], vu[2*p+1][1],
                                  Vst_b + v_off + ks*(16*AKV_ROW_B) + p*32);
                const uint32_t pa00 = e[0][2*ks][0], pa01 = e[0][2*ks][1];
                const uint32_t pa02 = e[0][2*ks+1][0], pa03 = e[0][2*ks+1][1];
                const uint32_t pa10 = e[1][2*ks][0], pa11 = e[1][2*ks][1];
                const uint32_t pa12 = e[1][2*ks+1][0], pa13 = e[1][2*ks+1][1];
#pragma unroll
                for (int ni = 0; ni < 8; ni++) {
                    mma_f16(o[0][ni][0], o[0][ni][1], o[0][ni][2], o[0][ni][3],
                            pa00, pa01, pa02, pa03, vu[ni][0], vu[ni][1]);
                    mma_f16(o[1][ni][0], o[1][ni][1], o[1][ni][2], o[1][ni][3],
                            pa10, pa11, pa12, pa13, vu[ni][0], vu[ni][1]);
                }
                mma_f16(la[0][0], la[0][1], la[0][2], la[0][3],
                        pa00, pa01, pa02, pa03, ONES_H2, ONES_H2);
                mma_f16(la[1][0], la[1][1], la[1][2], la[1][3],
                        pa10, pa11, pa12, pa13, ONES_H2, ONES_H2);
            }
        }
    }

    // ---- epilogue: ctx(f16) = O / l
#pragma unroll
    for (int mi = 0; mi < 2; mi++) {
        float inv0 = 1.f / la[mi][0], inv1 = 1.f / la[mi][2];
        const int q_r0 = q0 + w*32 + mi*16 + g;
#pragma unroll
        for (int ni = 0; ni < 8; ni++) {
            const int d = h*64 + ni*8 + 2*t4;
            *(uint32_t*)&ctx[(size_t)(b * SS + q_r0    ) * DD + d] =
                packh2(o[mi][ni][0]*inv0, o[mi][ni][1]*inv0);
            *(uint32_t*)&ctx[(size_t)(b * SS + q_r0 + 8) * DD + d] =
                packh2(o[mi][ni][2]*inv1, o[mi][ni][3]*inv1);
        }
    }
}

// ---------------------------------------------------------------------------
extern "C" void kernel_launch(void* const* d_in, const int* in_sizes, int n_in,
                              void* d_out, int out_size)
{
    const float* x  = (const float*)d_in[0];
    const float* Wq = (const float*)d_in[1];
    const float* bq = (const float*)d_in[2];
    const float* Wk = (const float*)d_in[3];
    const float* bk = (const float*)d_in[4];
    const float* Wv = (const float*)d_in[5];
    const float* bv = (const float*)d_in[6];
    const float* Wo = (const float*)d_in[7];
    const float* bo = (const float*)d_in[8];
    float* out = (float*)d_out;

    __half *xh, *Wh, *Qh, *Kh, *Vh, *ctxh;
    cudaGetSymbolAddress((void**)&xh,   g_xh);
    cudaGetSymbolAddress((void**)&Wh,   g_Wh);
    cudaGetSymbolAddress((void**)&Qh,   g_Qh);
    cudaGetSymbolAddress((void**)&Kh,   g_Kh);
    cudaGetSymbolAddress((void**)&Vh,   g_Vh);
    cudaGetSymbolAddress((void**)&ctxh, g_ctxh);
    __half* Wh3 = Wh + 3*(size_t)DD*DD;

    // Prep: W transpose+convert and x->f16 in ONE launch
    prep_all<<<6144, 256>>>(x, Wq, Wk, Wv, Wo, Wh, xh);

    cudaFuncSetAttribute((const void*)gemm_big<true>,
                         cudaFuncAttributeMaxDynamicSharedMemorySize, GEMM_SMEM);
    cudaFuncSetAttribute((const void*)gemm_big<false>,
                         cudaFuncAttributeMaxDynamicSharedMemorySize, GEMM_SMEM);
    cudaFuncSetAttribute((const void*)attn_h6,
                         cudaFuncAttributeMaxDynamicSharedMemorySize, ATT_SMEM);

    // Fused QKV projection: N = 3072 (Wq|Wk|Wv contiguous in g_Wh)
    gemm_big<true><<<dim3(3*DD/128, MM/128), 128, GEMM_SMEM>>>(
        xh, Wh, bq, bk, bv, Qh, Kh, Vh, nullptr);

    attn_h6<<<dim3(SS / 128, HH, BB), 128, ATT_SMEM>>>(Qh, Kh, Vh, ctxh);

    // Output projection (fp32 out + bo)
    gemm_big<false><<<dim3(DD/128, MM/128), 128, GEMM_SMEM>>>(
        ctxh, Wh3, bo, nullptr, nullptr, nullptr, nullptr, nullptr, out);
}